// round 9
// baseline (speedup 1.0000x reference)
#include <cuda_runtime.h>

// Inverted index scratch. g_head[row]: 0 = empty, else eid+1.
// g_next[eid]: 0 = end, else next_eid+1.  eid = b*Kp1 + k == output offset.
// g_head is zero at module load; the fused kernel's epilogue resets every
// head it consumed back to 0, so each launch (and graph replay) starts clean.
#define MAX_N (1 << 20)        // >= 1,000,000 rows
#define MAX_E (1 << 21)        // >= 1,048,832 entries
__device__ int g_head[MAX_N];
__device__ int g_next[MAX_E];

// Non-CSE-able vector load: keeps the copy-phase v[] registers DEAD during
// chain work (compiler cannot merge this with the earlier loads, so the row
// live-range ends at the copy stores). These re-reads are L2 hits.
__device__ __forceinline__ float4 ldg_f4_fresh(const float4* p) {
    float4 r;
    asm volatile("ld.global.nc.v4.f32 {%0,%1,%2,%3}, [%4];"
                 : "=f"(r.x), "=f"(r.y), "=f"(r.z), "=f"(r.w)
                 : "l"(p));
    return r;
}

// ----------------------------------------------------------------------------
// Kernel B: bin score entries into per-row chains (eid+1 encoding).
// ----------------------------------------------------------------------------
__global__ void bin_kernel(const int* __restrict__ idx, int Kp1) {
    int k = blockIdx.x * blockDim.x + threadIdx.x;
    int b = blockIdx.y;
    if (k >= Kp1) return;
    int eid = b * Kp1 + k;
    int row = idx[eid];
    g_next[eid] = atomicExch(&g_head[row], eid + 1);
}

// ----------------------------------------------------------------------------
// Kernel C: fused copy + scores + positive momentum update.
// One warp per 8 consecutive rows, exact coverage (no bounds checks).
// Phase 1 (register-light streaming): 8 batched LDG.128, 8 head loads,
//   8 batched STG.128 -> row registers die here.
// Phase 2 (rare-ish, serial per row): re-fetch the row from src via a fresh
//   L2-hit load, walk its chain (avg 1.05 entries), write scores; momentum
//   rows get an overwriting store. Peak live set stays small -> high occupancy
//   -> copy stream keeps DRAM saturated.
// Epilogue: reset this warp's heads to 0 for the next launch / graph replay.
// ----------------------------------------------------------------------------
#define RPW 8

template <int KP1C, bool EXACT>
__global__ void __launch_bounds__(256, 4)
fused_copy_score_kernel(const float4* __restrict__ mem4,
                        float4* __restrict__ dst4,
                        const float4* __restrict__ x4,
                        float* __restrict__ out,
                        int N, int Kp1_rt, float invT) {
    const int Kp1 = (KP1C > 0) ? KP1C : Kp1_rt;
    const int lane = threadIdx.x & 31;
    const int wg = (blockIdx.x * blockDim.x + threadIdx.x) >> 5;
    const int r0 = wg * RPW;
    if (!EXACT && r0 >= N) return;

    const float4* __restrict__ src = mem4 + (size_t)r0 * 32 + lane;
    float4*       __restrict__ dst = dst4 + (size_t)r0 * 32 + lane;

    // ---- Phase 1: pure copy stream ----
    int hd[RPW];
    {
        float4 v[RPW];
        #pragma unroll
        for (int j = 0; j < RPW; j++) {
            if (EXACT || r0 + j < N) v[j] = src[j * 32];   // LDG.128 [R+512j]
        }
        #pragma unroll
        for (int j = 0; j < RPW; j++) {
            hd[j] = (EXACT || r0 + j < N) ? g_head[r0 + j] : 0;
        }
        #pragma unroll
        for (int j = 0; j < RPW; j++) {
            if (EXACT || r0 + j < N) dst[j * 32] = v[j];   // STG.128 [R+512j]
        }
    }   // v[] dead here

    // ---- Early out only if EVERY row in the group is empty ----
    int any = 0;
    #pragma unroll
    for (int j = 0; j < RPW; j++) any |= hd[j];
    if (any == 0) return;            // heads already 0; no reset needed

    // ---- Phase 2: per-row chain walk with fresh L2-hit row loads ----
    #pragma unroll 1
    for (int j = 0; j < RPW; j++) {
        int ee = hd[j];
        if (ee == 0) continue;

        float4 rv = ldg_f4_fresh(src + j * 32);            // L2 hit
        int posb = -1;

        while (ee > 0) {
            int eid = ee - 1;
            unsigned int b = (unsigned int)eid / (unsigned int)Kp1;
            int k = eid - (int)b * Kp1;
            float4 xv = x4[b * 32 + lane];                 // L1/L2-resident
            float s = rv.x * xv.x + rv.y * xv.y
                    + rv.z * xv.z + rv.w * xv.w;
            #pragma unroll
            for (int o = 16; o > 0; o >>= 1)
                s += __shfl_xor_sync(0xffffffffu, s, o);
            if (lane == 0) out[eid] = s * invT;
            if (k == 0) posb = max(posb, (int)b);
            ee = g_next[eid];
        }

        // Momentum update overwrite (~256 rows grid-wide)
        if (posb >= 0) {
            float4 xv = x4[posb * 32 + lane];
            float4 w;
            w.x = 0.5f * rv.x + 0.5f * xv.x;
            w.y = 0.5f * rv.y + 0.5f * xv.y;
            w.z = 0.5f * rv.z + 0.5f * xv.z;
            w.w = 0.5f * rv.w + 0.5f * xv.w;
            float ss = w.x * w.x + w.y * w.y + w.z * w.z + w.w * w.w;
            #pragma unroll
            for (int o = 16; o > 0; o >>= 1)
                ss += __shfl_xor_sync(0xffffffffu, ss, o);
            float inv = 1.0f / sqrtf(ss);
            w.x *= inv; w.y *= inv; w.z *= inv; w.w *= inv;
            dst[j * 32] = w;
        }
    }

    // ---- Reset this warp's heads for the next launch / graph replay ----
    if (lane < RPW) {
        if (EXACT || r0 + lane < N) g_head[r0 + lane] = 0;
    }
}

// ----------------------------------------------------------------------------
// Launch. Inputs: x [B,D] f32, memory [N,D] f32, y [B] i32, idx [B,K+1] i32.
// Output: out [B,K+1] f32 then new_memory [N,D] f32.
// ----------------------------------------------------------------------------
extern "C" void kernel_launch(void* const* d_in, const int* in_sizes, int n_in,
                              void* d_out, int out_size) {
    const float* x      = (const float*)d_in[0];
    const float* memory = (const float*)d_in[1];
    const int*   idx    = (const int*)d_in[3];

    int B   = in_sizes[2];                  // 256
    int D   = in_sizes[0] / B;              // 128
    int Kp1 = in_sizes[3] / B;              // 4097
    int N   = in_sizes[1] / D;              // 1,000,000

    float* out_scores = (float*)d_out;
    float* new_memory = (float*)d_out + (long long)in_sizes[3];

    const float invT = 1.0f / 0.07f;

    // B) bin score entries by memory row
    {
        dim3 grid((Kp1 + 255) / 256, B);
        bin_kernel<<<grid, 256>>>(idx, Kp1);
    }

    // C) fused copy + scores + positive update
    {
        int threads = 256;                           // 8 warps/block
        int rows_per_block = (threads / 32) * RPW;   // 64
        int blocks = (N + rows_per_block - 1) / rows_per_block;
        bool exact = (N % rows_per_block) == 0;      // 1e6 / 64 = 15625 exact
        if (Kp1 == 4097 && exact) {
            fused_copy_score_kernel<4097, true><<<blocks, threads>>>(
                (const float4*)memory, (float4*)new_memory,
                (const float4*)x, out_scores, N, Kp1, invT);
        } else if (exact) {
            fused_copy_score_kernel<0, true><<<blocks, threads>>>(
                (const float4*)memory, (float4*)new_memory,
                (const float4*)x, out_scores, N, Kp1, invT);
        } else {
            fused_copy_score_kernel<0, false><<<blocks, threads>>>(
                (const float4*)memory, (float4*)new_memory,
                (const float4*)x, out_scores, N, Kp1, invT);
        }
    }
}

// round 10
// speedup vs baseline: 1.1966x; 1.1966x over previous
#include <cuda_runtime.h>

// Inverted index scratch. g_head[row]: 0 = empty, else eid+1.
// g_next[eid]: 0 = end, else next_eid+1.  eid = b*Kp1 + k == output offset.
// g_head is zero at module load; the fused kernel's epilogue resets every
// head it consumed back to 0, so each launch (and graph replay) starts clean.
#define MAX_N (1 << 20)        // >= 1,000,000 rows
#define MAX_E (1 << 21)        // >= 1,048,832 entries
__device__ int g_head[MAX_N];
__device__ int g_next[MAX_E];

// Non-forwardable LDS: compiler cannot CSE this back to the registers that
// produced the stashed values, so the copy-phase v[] truly dies at the stores.
__device__ __forceinline__ float4 lds_f4_fresh(const float4* p) {
    float4 r;
    unsigned saddr = (unsigned)__cvta_generic_to_shared(p);
    asm volatile("ld.shared.v4.f32 {%0,%1,%2,%3}, [%4];"
                 : "=f"(r.x), "=f"(r.y), "=f"(r.z), "=f"(r.w)
                 : "r"(saddr));
    return r;
}

// ----------------------------------------------------------------------------
// Kernel B: bin score entries into per-row chains (eid+1 encoding).
// ----------------------------------------------------------------------------
__global__ void bin_kernel(const int* __restrict__ idx, int Kp1) {
    int k = blockIdx.x * blockDim.x + threadIdx.x;
    int b = blockIdx.y;
    if (k >= Kp1) return;
    int eid = b * Kp1 + k;
    int row = idx[eid];
    g_next[eid] = atomicExch(&g_head[row], eid + 1);
}

// ----------------------------------------------------------------------------
// Kernel C: fused copy + scores + positive momentum update.
// One warp per 8 consecutive rows, exact coverage.
// Phase 1: batched copy stream (8 LDG.128, 8 head loads, 8 STG.128) + stash
//   each row into this warp's smem slot (STS.128, same-thread readback, no
//   sync). Row registers die here -> low peak pressure -> high occupancy.
// Phase 2 (R8-proven batched structure): first entries of all 8 rows
//   processed together — batched g_next loads, batched smem row reloads
//   (independent LDS, 29cyc), one interleaved 8-wide shfl reduction.
//   Chains >= 2 take rare serial tails. Momentum rows get an overwriting
//   store. Epilogue resets this warp's heads.
// ----------------------------------------------------------------------------
#define RPW 8

template <int KP1C, bool EXACT>
__global__ void __launch_bounds__(256, 4)
fused_copy_score_kernel(const float4* __restrict__ mem4,
                        float4* __restrict__ dst4,
                        const float4* __restrict__ x4,
                        float* __restrict__ out,
                        int N, int Kp1_rt, float invT) {
    const int Kp1 = (KP1C > 0) ? KP1C : Kp1_rt;
    const int lane = threadIdx.x & 31;
    const int wlocal = threadIdx.x >> 5;                 // 0..7
    const int wg = (blockIdx.x * blockDim.x + threadIdx.x) >> 5;
    const int r0 = wg * RPW;
    if (!EXACT && r0 >= N) return;

    // 8 warps x 8 rows x 32 lanes x 16B = 32 KB
    __shared__ float4 stash[8 * RPW * 32];
    float4* my = &stash[wlocal * (RPW * 32) + lane];

    const float4* __restrict__ src = mem4 + (size_t)r0 * 32 + lane;
    float4*       __restrict__ dst = dst4 + (size_t)r0 * 32 + lane;

    // ---- Phase 1: pure copy stream + smem stash ----
    int hd[RPW];
    {
        float4 v[RPW];
        #pragma unroll
        for (int j = 0; j < RPW; j++) {
            if (EXACT || r0 + j < N) v[j] = src[j * 32];   // LDG.128
        }
        #pragma unroll
        for (int j = 0; j < RPW; j++) {
            hd[j] = (EXACT || r0 + j < N) ? g_head[r0 + j] : 0;
        }
        #pragma unroll
        for (int j = 0; j < RPW; j++) {
            if (EXACT || r0 + j < N) dst[j * 32] = v[j];   // STG.128
        }
        #pragma unroll
        for (int j = 0; j < RPW; j++) {
            my[j * 32] = v[j];                             // STS.128
        }
    }   // v[] dead here

    // ---- Early out only if EVERY row in the group is empty ----
    int any = 0;
    #pragma unroll
    for (int j = 0; j < RPW; j++) any |= hd[j];
    if (any == 0) return;            // heads already 0; no reset needed

    int posb[RPW];
    #pragma unroll
    for (int j = 0; j < RPW; j++) posb[j] = -1;

    // ---- First entries: batched, full ILP, single interleaved reduction ----
    int e[RPW], nxt[RPW];
    float s[RPW];
    #pragma unroll
    for (int j = 0; j < RPW; j++) {
        e[j] = hd[j];
        nxt[j] = (e[j] > 0) ? g_next[e[j] - 1] : 0;
    }
    #pragma unroll
    for (int j = 0; j < RPW; j++) {
        if (e[j] > 0) {
            unsigned int b = (unsigned int)(e[j] - 1) / (unsigned int)Kp1;
            float4 xv = x4[b * 32 + lane];                 // L1/L2-resident
            float4 rv = lds_f4_fresh(my + j * 32);         // independent LDS
            s[j] = rv.x * xv.x + rv.y * xv.y
                 + rv.z * xv.z + rv.w * xv.w;
        } else {
            s[j] = 0.0f;
        }
    }
    #pragma unroll
    for (int o = 16; o > 0; o >>= 1) {
        #pragma unroll
        for (int j = 0; j < RPW; j++) {
            s[j] += __shfl_xor_sync(0xffffffffu, s[j], o);
        }
    }
    #pragma unroll
    for (int j = 0; j < RPW; j++) {
        if (e[j] > 0) {
            int eid = e[j] - 1;
            unsigned int b = (unsigned int)eid / (unsigned int)Kp1;
            int k = eid - (int)b * Kp1;
            if (lane == 0) out[eid] = s[j] * invT;
            if (k == 0) posb[j] = max(posb[j], (int)b);
        }
    }

    // ---- Continuation for chains of length >= 2 (rare) ----
    #pragma unroll
    for (int j = 0; j < RPW; j++) {
        int ee = nxt[j];
        while (ee > 0) {
            int eid = ee - 1;
            unsigned int b = (unsigned int)eid / (unsigned int)Kp1;
            int k = eid - (int)b * Kp1;
            float4 xv = x4[b * 32 + lane];
            float4 rv = lds_f4_fresh(my + j * 32);
            float ss = rv.x * xv.x + rv.y * xv.y
                     + rv.z * xv.z + rv.w * xv.w;
            #pragma unroll
            for (int o = 16; o > 0; o >>= 1)
                ss += __shfl_xor_sync(0xffffffffu, ss, o);
            if (lane == 0) out[eid] = ss * invT;
            if (k == 0) posb[j] = max(posb[j], (int)b);
            ee = g_next[eid];
        }
    }

    // ---- Momentum update overwrite (~256 rows grid-wide) ----
    #pragma unroll
    for (int j = 0; j < RPW; j++) {
        if (posb[j] >= 0) {
            float4 xv = x4[posb[j] * 32 + lane];
            float4 rv = lds_f4_fresh(my + j * 32);
            float4 w;
            w.x = 0.5f * rv.x + 0.5f * xv.x;
            w.y = 0.5f * rv.y + 0.5f * xv.y;
            w.z = 0.5f * rv.z + 0.5f * xv.z;
            w.w = 0.5f * rv.w + 0.5f * xv.w;
            float ss = w.x * w.x + w.y * w.y + w.z * w.z + w.w * w.w;
            #pragma unroll
            for (int o = 16; o > 0; o >>= 1)
                ss += __shfl_xor_sync(0xffffffffu, ss, o);
            float inv = 1.0f / sqrtf(ss);
            w.x *= inv; w.y *= inv; w.z *= inv; w.w *= inv;
            dst[j * 32] = w;
        }
    }

    // ---- Reset this warp's heads for the next launch / graph replay ----
    if (lane < RPW) {
        if (EXACT || r0 + lane < N) g_head[r0 + lane] = 0;
    }
}

// ----------------------------------------------------------------------------
// Launch. Inputs: x [B,D] f32, memory [N,D] f32, y [B] i32, idx [B,K+1] i32.
// Output: out [B,K+1] f32 then new_memory [N,D] f32.
// ----------------------------------------------------------------------------
extern "C" void kernel_launch(void* const* d_in, const int* in_sizes, int n_in,
                              void* d_out, int out_size) {
    const float* x      = (const float*)d_in[0];
    const float* memory = (const float*)d_in[1];
    const int*   idx    = (const int*)d_in[3];

    int B   = in_sizes[2];                  // 256
    int D   = in_sizes[0] / B;              // 128
    int Kp1 = in_sizes[3] / B;              // 4097
    int N   = in_sizes[1] / D;              // 1,000,000

    float* out_scores = (float*)d_out;
    float* new_memory = (float*)d_out + (long long)in_sizes[3];

    const float invT = 1.0f / 0.07f;

    // B) bin score entries by memory row
    {
        dim3 grid((Kp1 + 255) / 256, B);
        bin_kernel<<<grid, 256>>>(idx, Kp1);
    }

    // C) fused copy + scores + positive update
    {
        int threads = 256;                           // 8 warps/block
        int rows_per_block = (threads / 32) * RPW;   // 64
        int blocks = (N + rows_per_block - 1) / rows_per_block;
        bool exact = (N % rows_per_block) == 0;      // 1e6 / 64 = 15625 exact
        if (Kp1 == 4097 && exact) {
            fused_copy_score_kernel<4097, true><<<blocks, threads>>>(
                (const float4*)memory, (float4*)new_memory,
                (const float4*)x, out_scores, N, Kp1, invT);
        } else if (exact) {
            fused_copy_score_kernel<0, true><<<blocks, threads>>>(
                (const float4*)memory, (float4*)new_memory,
                (const float4*)x, out_scores, N, Kp1, invT);
        } else {
            fused_copy_score_kernel<0, false><<<blocks, threads>>>(
                (const float4*)memory, (float4*)new_memory,
                (const float4*)x, out_scores, N, Kp1, invT);
        }
    }
}

// round 11
// speedup vs baseline: 1.3174x; 1.1010x over previous
#include <cuda_runtime.h>

// Inverted index scratch. g_head[row]: 0 = empty, else eid+1.
// g_next[eid]: 0 = end, else next_eid+1.  eid = b*Kp1 + k == output offset.
// g_head is zero at module load; the fused kernel's epilogue resets every
// head it consumed back to 0, so each launch (and graph replay) starts clean.
#define MAX_N (1 << 20)        // >= 1,000,000 rows
#define MAX_E (1 << 21)        // >= 1,048,832 entries
__device__ int g_head[MAX_N];
__device__ int g_next[MAX_E];

// Non-forwardable LDS: compiler cannot CSE this back to the registers that
// produced the stashed values, so the copy-phase v[] truly dies at the stores.
__device__ __forceinline__ float4 lds_f4_fresh(const float4* p) {
    float4 r;
    unsigned saddr = (unsigned)__cvta_generic_to_shared(p);
    asm volatile("ld.shared.v4.f32 {%0,%1,%2,%3}, [%4];"
                 : "=f"(r.x), "=f"(r.y), "=f"(r.z), "=f"(r.w)
                 : "r"(saddr));
    return r;
}

// ----------------------------------------------------------------------------
// Kernel B: bin score entries into per-row chains (eid+1 encoding).
// ----------------------------------------------------------------------------
__global__ void bin_kernel(const int* __restrict__ idx, int Kp1) {
    int k = blockIdx.x * blockDim.x + threadIdx.x;
    int b = blockIdx.y;
    if (k >= Kp1) return;
    int eid = b * Kp1 + k;
    int row = idx[eid];
    g_next[eid] = atomicExch(&g_head[row], eid + 1);
}

// ----------------------------------------------------------------------------
// Kernel C: fused copy + scores + positive momentum update.
// One warp per RPW=4 consecutive rows, exact coverage.
// Phase 1: batched copy stream (4 LDG.128, 4 head loads, 4 STG.128) + smem
//   stash (STS.128, same-thread readback, no sync). Row regs die here.
// Phase 2: first entries of all 4 rows batched (one interleaved 4-wide shfl
//   reduction, rows re-read from smem); chains >= 2 take rare serial tails;
//   momentum rows get an overwriting store; epilogue resets heads.
// RPW=4 + launch_bounds(256,5): 5 blocks/SM (40 warps) and half-length chain
//   tails -> more independent streams covering each tail.
// ----------------------------------------------------------------------------
#define RPW 4

template <int KP1C, bool EXACT>
__global__ void __launch_bounds__(256, 5)
fused_copy_score_kernel(const float4* __restrict__ mem4,
                        float4* __restrict__ dst4,
                        const float4* __restrict__ x4,
                        float* __restrict__ out,
                        int N, int Kp1_rt, float invT) {
    const int Kp1 = (KP1C > 0) ? KP1C : Kp1_rt;
    const int lane = threadIdx.x & 31;
    const int wlocal = threadIdx.x >> 5;                 // 0..7
    const int wg = (blockIdx.x * blockDim.x + threadIdx.x) >> 5;
    const int r0 = wg * RPW;
    if (!EXACT && r0 >= N) return;

    // 8 warps x 4 rows x 32 lanes x 16B = 16 KB
    __shared__ float4 stash[8 * RPW * 32];
    float4* my = &stash[wlocal * (RPW * 32) + lane];

    const float4* __restrict__ src = mem4 + (size_t)r0 * 32 + lane;
    float4*       __restrict__ dst = dst4 + (size_t)r0 * 32 + lane;

    // ---- Phase 1: pure copy stream + smem stash ----
    int hd[RPW];
    {
        float4 v[RPW];
        #pragma unroll
        for (int j = 0; j < RPW; j++) {
            if (EXACT || r0 + j < N) v[j] = src[j * 32];   // LDG.128
        }
        #pragma unroll
        for (int j = 0; j < RPW; j++) {
            hd[j] = (EXACT || r0 + j < N) ? g_head[r0 + j] : 0;
        }
        #pragma unroll
        for (int j = 0; j < RPW; j++) {
            if (EXACT || r0 + j < N) dst[j * 32] = v[j];   // STG.128
        }
        #pragma unroll
        for (int j = 0; j < RPW; j++) {
            my[j * 32] = v[j];                             // STS.128
        }
    }   // v[] dead here

    // ---- Early out only if EVERY row in the group is empty ----
    int any = 0;
    #pragma unroll
    for (int j = 0; j < RPW; j++) any |= hd[j];
    if (any == 0) return;            // heads already 0; no reset needed

    int posb[RPW];
    #pragma unroll
    for (int j = 0; j < RPW; j++) posb[j] = -1;

    // ---- First entries: batched, full ILP, single interleaved reduction ----
    int e[RPW], nxt[RPW];
    float s[RPW];
    #pragma unroll
    for (int j = 0; j < RPW; j++) {
        e[j] = hd[j];
        nxt[j] = (e[j] > 0) ? g_next[e[j] - 1] : 0;
    }
    #pragma unroll
    for (int j = 0; j < RPW; j++) {
        if (e[j] > 0) {
            unsigned int b = (unsigned int)(e[j] - 1) / (unsigned int)Kp1;
            float4 xv = x4[b * 32 + lane];                 // L1/L2-resident
            float4 rv = lds_f4_fresh(my + j * 32);         // independent LDS
            s[j] = rv.x * xv.x + rv.y * xv.y
                 + rv.z * xv.z + rv.w * xv.w;
        } else {
            s[j] = 0.0f;
        }
    }
    #pragma unroll
    for (int o = 16; o > 0; o >>= 1) {
        #pragma unroll
        for (int j = 0; j < RPW; j++) {
            s[j] += __shfl_xor_sync(0xffffffffu, s[j], o);
        }
    }
    #pragma unroll
    for (int j = 0; j < RPW; j++) {
        if (e[j] > 0) {
            int eid = e[j] - 1;
            unsigned int b = (unsigned int)eid / (unsigned int)Kp1;
            int k = eid - (int)b * Kp1;
            if (lane == 0) out[eid] = s[j] * invT;
            if (k == 0) posb[j] = max(posb[j], (int)b);
        }
    }

    // ---- Continuation for chains of length >= 2 (rare) ----
    #pragma unroll
    for (int j = 0; j < RPW; j++) {
        int ee = nxt[j];
        while (ee > 0) {
            int eid = ee - 1;
            unsigned int b = (unsigned int)eid / (unsigned int)Kp1;
            int k = eid - (int)b * Kp1;
            float4 xv = x4[b * 32 + lane];
            float4 rv = lds_f4_fresh(my + j * 32);
            float ss = rv.x * xv.x + rv.y * xv.y
                     + rv.z * xv.z + rv.w * xv.w;
            #pragma unroll
            for (int o = 16; o > 0; o >>= 1)
                ss += __shfl_xor_sync(0xffffffffu, ss, o);
            if (lane == 0) out[eid] = ss * invT;
            if (k == 0) posb[j] = max(posb[j], (int)b);
            ee = g_next[eid];
        }
    }

    // ---- Momentum update overwrite (~256 rows grid-wide) ----
    #pragma unroll
    for (int j = 0; j < RPW; j++) {
        if (posb[j] >= 0) {
            float4 xv = x4[posb[j] * 32 + lane];
            float4 rv = lds_f4_fresh(my + j * 32);
            float4 w;
            w.x = 0.5f * rv.x + 0.5f * xv.x;
            w.y = 0.5f * rv.y + 0.5f * xv.y;
            w.z = 0.5f * rv.z + 0.5f * xv.z;
            w.w = 0.5f * rv.w + 0.5f * xv.w;
            float ss = w.x * w.x + w.y * w.y + w.z * w.z + w.w * w.w;
            #pragma unroll
            for (int o = 16; o > 0; o >>= 1)
                ss += __shfl_xor_sync(0xffffffffu, ss, o);
            float inv = 1.0f / sqrtf(ss);
            w.x *= inv; w.y *= inv; w.z *= inv; w.w *= inv;
            dst[j * 32] = w;
        }
    }

    // ---- Reset this warp's heads for the next launch / graph replay ----
    if (lane < RPW) {
        if (EXACT || r0 + lane < N) g_head[r0 + lane] = 0;
    }
}

// ----------------------------------------------------------------------------
// Launch. Inputs: x [B,D] f32, memory [N,D] f32, y [B] i32, idx [B,K+1] i32.
// Output: out [B,K+1] f32 then new_memory [N,D] f32.
// ----------------------------------------------------------------------------
extern "C" void kernel_launch(void* const* d_in, const int* in_sizes, int n_in,
                              void* d_out, int out_size) {
    const float* x      = (const float*)d_in[0];
    const float* memory = (const float*)d_in[1];
    const int*   idx    = (const int*)d_in[3];

    int B   = in_sizes[2];                  // 256
    int D   = in_sizes[0] / B;              // 128
    int Kp1 = in_sizes[3] / B;              // 4097
    int N   = in_sizes[1] / D;              // 1,000,000

    float* out_scores = (float*)d_out;
    float* new_memory = (float*)d_out + (long long)in_sizes[3];

    const float invT = 1.0f / 0.07f;

    // B) bin score entries by memory row
    {
        dim3 grid((Kp1 + 255) / 256, B);
        bin_kernel<<<grid, 256>>>(idx, Kp1);
    }

    // C) fused copy + scores + positive update
    {
        int threads = 256;                           // 8 warps/block
        int rows_per_block = (threads / 32) * RPW;   // 32
        int blocks = (N + rows_per_block - 1) / rows_per_block;
        bool exact = (N % rows_per_block) == 0;      // 1e6 / 32 = 31250 exact
        if (Kp1 == 4097 && exact) {
            fused_copy_score_kernel<4097, true><<<blocks, threads>>>(
                (const float4*)memory, (float4*)new_memory,
                (const float4*)x, out_scores, N, Kp1, invT);
        } else if (exact) {
            fused_copy_score_kernel<0, true><<<blocks, threads>>>(
                (const float4*)memory, (float4*)new_memory,
                (const float4*)x, out_scores, N, Kp1, invT);
        } else {
            fused_copy_score_kernel<0, false><<<blocks, threads>>>(
                (const float4*)memory, (float4*)new_memory,
                (const float4*)x, out_scores, N, Kp1, invT);
        }
    }
}

// round 12
// speedup vs baseline: 1.4519x; 1.1021x over previous
#include <cuda_runtime.h>

// Inverted index scratch. g_head[row]: 0 = empty, else eid+1.
// g_next[eid]: 0 = end, else next_eid+1.  eid = b*Kp1 + k == output offset.
// g_head is zero at module load; the fused kernel's epilogue resets every
// head it consumed back to 0, so each launch (and graph replay) starts clean.
#define MAX_N (1 << 20)        // >= 1,000,000 rows
#define MAX_E (1 << 21)        // >= 1,048,832 entries
__device__ int g_head[MAX_N];
__device__ int g_next[MAX_E];

// Non-forwardable LDS: compiler cannot CSE this back to the registers that
// produced the stashed values, so the copy-phase v[] truly dies at the stores.
__device__ __forceinline__ float4 lds_f4_fresh(const float4* p) {
    float4 r;
    unsigned saddr = (unsigned)__cvta_generic_to_shared(p);
    asm volatile("ld.shared.v4.f32 {%0,%1,%2,%3}, [%4];"
                 : "=f"(r.x), "=f"(r.y), "=f"(r.z), "=f"(r.w)
                 : "r"(saddr));
    return r;
}

// ----------------------------------------------------------------------------
// Kernel B: bin score entries into per-row chains (eid+1 encoding).
// ----------------------------------------------------------------------------
__global__ void bin_kernel(const int* __restrict__ idx, int Kp1) {
    int k = blockIdx.x * blockDim.x + threadIdx.x;
    int b = blockIdx.y;
    if (k >= Kp1) return;
    int eid = b * Kp1 + k;
    int row = idx[eid];
    g_next[eid] = atomicExch(&g_head[row], eid + 1);
}

// ----------------------------------------------------------------------------
// Kernel C: fused copy + scores + positive momentum update.
// One warp per RPW=2 consecutive rows, exact coverage.
// Phase 1: batched copy stream (2 LDG.128, 2 head loads, 2 STG.128) + smem
//   stash (STS.128, same-thread readback, no sync). Row regs die here.
// Phase 2: first entries of both rows batched (one interleaved 2-wide shfl
//   reduction, rows re-read from smem); chains >= 2 take rare serial tails;
//   momentum rows get an overwriting store; epilogue resets heads.
// RPW=2 + launch_bounds(256,6): 6 blocks/SM (48 warps) with minimal per-warp
//   footprint -> maximal independent streams covering each chain tail.
// ----------------------------------------------------------------------------
#define RPW 2

template <int KP1C, bool EXACT>
__global__ void __launch_bounds__(256, 6)
fused_copy_score_kernel(const float4* __restrict__ mem4,
                        float4* __restrict__ dst4,
                        const float4* __restrict__ x4,
                        float* __restrict__ out,
                        int N, int Kp1_rt, float invT) {
    const int Kp1 = (KP1C > 0) ? KP1C : Kp1_rt;
    const int lane = threadIdx.x & 31;
    const int wlocal = threadIdx.x >> 5;                 // 0..7
    const int wg = (blockIdx.x * blockDim.x + threadIdx.x) >> 5;
    const int r0 = wg * RPW;
    if (!EXACT && r0 >= N) return;

    // 8 warps x 2 rows x 32 lanes x 16B = 8 KB
    __shared__ float4 stash[8 * RPW * 32];
    float4* my = &stash[wlocal * (RPW * 32) + lane];

    const float4* __restrict__ src = mem4 + (size_t)r0 * 32 + lane;
    float4*       __restrict__ dst = dst4 + (size_t)r0 * 32 + lane;

    // ---- Phase 1: pure copy stream + smem stash ----
    int hd[RPW];
    {
        float4 v[RPW];
        #pragma unroll
        for (int j = 0; j < RPW; j++) {
            if (EXACT || r0 + j < N) v[j] = src[j * 32];   // LDG.128
        }
        #pragma unroll
        for (int j = 0; j < RPW; j++) {
            hd[j] = (EXACT || r0 + j < N) ? g_head[r0 + j] : 0;
        }
        #pragma unroll
        for (int j = 0; j < RPW; j++) {
            if (EXACT || r0 + j < N) dst[j * 32] = v[j];   // STG.128
        }
        #pragma unroll
        for (int j = 0; j < RPW; j++) {
            my[j * 32] = v[j];                             // STS.128
        }
    }   // v[] dead here

    // ---- Early out only if EVERY row in the group is empty (~12%) ----
    int any = 0;
    #pragma unroll
    for (int j = 0; j < RPW; j++) any |= hd[j];
    if (any == 0) return;            // heads already 0; no reset needed

    int posb[RPW];
    #pragma unroll
    for (int j = 0; j < RPW; j++) posb[j] = -1;

    // ---- First entries: batched, full ILP, single interleaved reduction ----
    int e[RPW], nxt[RPW];
    float s[RPW];
    #pragma unroll
    for (int j = 0; j < RPW; j++) {
        e[j] = hd[j];
        nxt[j] = (e[j] > 0) ? g_next[e[j] - 1] : 0;
    }
    #pragma unroll
    for (int j = 0; j < RPW; j++) {
        if (e[j] > 0) {
            unsigned int b = (unsigned int)(e[j] - 1) / (unsigned int)Kp1;
            float4 xv = x4[b * 32 + lane];                 // L1/L2-resident
            float4 rv = lds_f4_fresh(my + j * 32);         // independent LDS
            s[j] = rv.x * xv.x + rv.y * xv.y
                 + rv.z * xv.z + rv.w * xv.w;
        } else {
            s[j] = 0.0f;
        }
    }
    #pragma unroll
    for (int o = 16; o > 0; o >>= 1) {
        #pragma unroll
        for (int j = 0; j < RPW; j++) {
            s[j] += __shfl_xor_sync(0xffffffffu, s[j], o);
        }
    }
    #pragma unroll
    for (int j = 0; j < RPW; j++) {
        if (e[j] > 0) {
            int eid = e[j] - 1;
            unsigned int b = (unsigned int)eid / (unsigned int)Kp1;
            int k = eid - (int)b * Kp1;
            if (lane == 0) out[eid] = s[j] * invT;
            if (k == 0) posb[j] = max(posb[j], (int)b);
        }
    }

    // ---- Continuation for chains of length >= 2 (rare) ----
    #pragma unroll
    for (int j = 0; j < RPW; j++) {
        int ee = nxt[j];
        while (ee > 0) {
            int eid = ee - 1;
            unsigned int b = (unsigned int)eid / (unsigned int)Kp1;
            int k = eid - (int)b * Kp1;
            float4 xv = x4[b * 32 + lane];
            float4 rv = lds_f4_fresh(my + j * 32);
            float ss = rv.x * xv.x + rv.y * xv.y
                     + rv.z * xv.z + rv.w * xv.w;
            #pragma unroll
            for (int o = 16; o > 0; o >>= 1)
                ss += __shfl_xor_sync(0xffffffffu, ss, o);
            if (lane == 0) out[eid] = ss * invT;
            if (k == 0) posb[j] = max(posb[j], (int)b);
            ee = g_next[eid];
        }
    }

    // ---- Momentum update overwrite (~256 rows grid-wide) ----
    #pragma unroll
    for (int j = 0; j < RPW; j++) {
        if (posb[j] >= 0) {
            float4 xv = x4[posb[j] * 32 + lane];
            float4 rv = lds_f4_fresh(my + j * 32);
            float4 w;
            w.x = 0.5f * rv.x + 0.5f * xv.x;
            w.y = 0.5f * rv.y + 0.5f * xv.y;
            w.z = 0.5f * rv.z + 0.5f * xv.z;
            w.w = 0.5f * rv.w + 0.5f * xv.w;
            float ss = w.x * w.x + w.y * w.y + w.z * w.z + w.w * w.w;
            #pragma unroll
            for (int o = 16; o > 0; o >>= 1)
                ss += __shfl_xor_sync(0xffffffffu, ss, o);
            float inv = 1.0f / sqrtf(ss);
            w.x *= inv; w.y *= inv; w.z *= inv; w.w *= inv;
            dst[j * 32] = w;
        }
    }

    // ---- Reset this warp's heads for the next launch / graph replay ----
    if (lane < RPW) {
        if (EXACT || r0 + lane < N) g_head[r0 + lane] = 0;
    }
}

// ----------------------------------------------------------------------------
// Launch. Inputs: x [B,D] f32, memory [N,D] f32, y [B] i32, idx [B,K+1] i32.
// Output: out [B,K+1] f32 then new_memory [N,D] f32.
// ----------------------------------------------------------------------------
extern "C" void kernel_launch(void* const* d_in, const int* in_sizes, int n_in,
                              void* d_out, int out_size) {
    const float* x      = (const float*)d_in[0];
    const float* memory = (const float*)d_in[1];
    const int*   idx    = (const int*)d_in[3];

    int B   = in_sizes[2];                  // 256
    int D   = in_sizes[0] / B;              // 128
    int Kp1 = in_sizes[3] / B;              // 4097
    int N   = in_sizes[1] / D;              // 1,000,000

    float* out_scores = (float*)d_out;
    float* new_memory = (float*)d_out + (long long)in_sizes[3];

    const float invT = 1.0f / 0.07f;

    // B) bin score entries by memory row
    {
        dim3 grid((Kp1 + 255) / 256, B);
        bin_kernel<<<grid, 256>>>(idx, Kp1);
    }

    // C) fused copy + scores + positive update
    {
        int threads = 256;                           // 8 warps/block
        int rows_per_block = (threads / 32) * RPW;   // 16
        int blocks = (N + rows_per_block - 1) / rows_per_block;
        bool exact = (N % rows_per_block) == 0;      // 1e6 / 16 = 62500 exact
        if (Kp1 == 4097 && exact) {
            fused_copy_score_kernel<4097, true><<<blocks, threads>>>(
                (const float4*)memory, (float4*)new_memory,
                (const float4*)x, out_scores, N, Kp1, invT);
        } else if (exact) {
            fused_copy_score_kernel<0, true><<<blocks, threads>>>(
                (const float4*)memory, (float4*)new_memory,
                (const float4*)x, out_scores, N, Kp1, invT);
        } else {
            fused_copy_score_kernel<0, false><<<blocks, threads>>>(
                (const float4*)memory, (float4*)new_memory,
                (const float4*)x, out_scores, N, Kp1, invT);
        }
    }
}